// round 1
// baseline (speedup 1.0000x reference)
#include <cuda_runtime.h>
#include <math.h>

#define BATCHN 128
#define NDIM   128
#define KDIM   64
#define NL     6
#define BN_EPS 1e-5f

// ---------------- device scratch (static; no allocation) ----------------
__device__ float g_C[(size_t)NL*BATCHN*NDIM*NDIM];   // [l][b][n][m]  48 MB
__device__ float g_d[NL*BATCHN*NDIM];                // [l][b][m]
__device__ float g_pre[BATCHN*NDIM];                 // out_x before BN
__device__ float g_xe[BATCHN*NDIM];                  // current x_est
__device__ float g_mu[NDIM];
__device__ float g_rstd[NDIM];
__device__ int   g_nzidx[BATCHN*NDIM];
__device__ int   g_nzcnt[BATCHN];
__device__ float g_part[NL*512];                     // per-block loss partials

// ---------------- K1: C_l[b,n,m] = sum_k BB[b,n,m,k]*wKL[l,k,m] ---------
// grid (4 m-tiles, 128 b), 256 threads = 32 m x 8 k-groups
__global__ void k_buildC(const float* __restrict__ BB, const float* __restrict__ wKL)
{
    const int m0   = blockIdx.x * 32;
    const int b    = blockIdx.y;
    const int mloc = threadIdx.x >> 3;   // 0..31
    const int tk   = threadIdx.x & 7;    // 0..7 (k = tk*8 + kk)
    const int m    = m0 + mloc;

    // per-thread slice of wKL, reused across all 128 n
    float w[6][8];
#pragma unroll
    for (int l = 0; l < 6; l++)
#pragma unroll
        for (int kk = 0; kk < 8; kk++)
            w[l][kk] = wKL[(l*64 + tk*8 + kk)*128 + m];

    const float4* BB4 = reinterpret_cast<const float4*>(BB);
    const size_t off0 = (size_t)b*262144 + (size_t)m*16 + tk*2;

    for (int n = 0; n < 128; n++) {
        const float4* p = BB4 + off0 + (size_t)n*2048;
        float4 v0 = p[0];
        float4 v1 = p[1];
        float vv[8] = {v0.x, v0.y, v0.z, v0.w, v1.x, v1.y, v1.z, v1.w};
        float acc[6] = {0.f, 0.f, 0.f, 0.f, 0.f, 0.f};
#pragma unroll
        for (int kk = 0; kk < 8; kk++) {
            float xv = vv[kk];
#pragma unroll
            for (int l = 0; l < 6; l++)
                acc[l] = fmaf(xv, w[l][kk], acc[l]);
        }
#pragma unroll
        for (int l = 0; l < 6; l++) {
            float a = acc[l];
            a += __shfl_down_sync(0xffffffffu, a, 4, 8);
            a += __shfl_down_sync(0xffffffffu, a, 2, 8);
            a += __shfl_down_sync(0xffffffffu, a, 1, 8);
            if (tk == 0)
                g_C[(((size_t)l*128 + b)*128 + n)*128 + m] = a;
        }
    }
}

// ---------------- K2: d_l[b,m] = sum_k zB[b,m,k]*wKL[l,k,m] -------------
__global__ void k_buildD(const float* __restrict__ zB, const float* __restrict__ wKL)
{
    const int b = blockIdx.x;
    const int m = threadIdx.x;  // 128 threads
    __shared__ float s[128*65];
    const float* src = zB + (size_t)b*8192;
    for (int i = m; i < 8192; i += 128)
        s[(i >> 6)*65 + (i & 63)] = src[i];
    __syncthreads();
#pragma unroll
    for (int l = 0; l < 6; l++) {
        float acc = 0.f;
#pragma unroll
        for (int k = 0; k < 64; k++)
            acc = fmaf(s[m*65 + k], wKL[(l*64 + k)*128 + m], acc);
        g_d[(l*128 + b)*128 + m] = acc;
    }
}

// ---------------- K3: out_pre[b,m] = x*w_x - d + sum_n x[b,n]*C ---------
__global__ void k_pre(const float* __restrict__ xin, const float* __restrict__ wx,
                      int l, int from_input, int use_nz)
{
    const int b = blockIdx.x;
    const int m = threadIdx.x;  // 128
    __shared__ float xs[128];
    __shared__ int   idxs[128];
    __shared__ int   scnt;

    float xv = from_input ? xin[b*128 + m] : g_xe[b*128 + m];
    xs[m] = xv;
    if (use_nz) {
        idxs[m] = g_nzidx[b*128 + m];
        if (m == 0) scnt = g_nzcnt[b];
    }
    __syncthreads();

    float acc = fmaf(xv, wx[l*128 + m], -g_d[(l*128 + b)*128 + m]);
    const float* Cb = g_C + ((size_t)l*128 + b)*16384;

    if (use_nz) {
        const int c = scnt;
        int i = 0;
        for (; i + 4 <= c; i += 4) {
            int n0 = idxs[i], n1 = idxs[i+1], n2 = idxs[i+2], n3 = idxs[i+3];
            float c0 = Cb[n0*128 + m], c1 = Cb[n1*128 + m];
            float c2 = Cb[n2*128 + m], c3 = Cb[n3*128 + m];
            acc = fmaf(xs[n0], c0, acc);
            acc = fmaf(xs[n1], c1, acc);
            acc = fmaf(xs[n2], c2, acc);
            acc = fmaf(xs[n3], c3, acc);
        }
        for (; i < c; i++) {
            int n = idxs[i];
            acc = fmaf(xs[n], Cb[n*128 + m], acc);
        }
    } else {
#pragma unroll 4
        for (int n = 0; n < 128; n++)
            acc = fmaf(xs[n], Cb[n*128 + m], acc);
    }
    g_pre[b*128 + m] = acc;
}

// ---------------- K4: batch mean / rstd per feature (two-pass) ----------
__global__ void k_stats()
{
    const int m = threadIdx.x;  // grid 1, block 128
    float s = 0.f;
#pragma unroll 8
    for (int b = 0; b < 128; b++) s += g_pre[b*128 + m];
    const float mu = s * (1.f/128.f);
    float s2 = 0.f;
#pragma unroll 8
    for (int b = 0; b < 128; b++) {
        float d = g_pre[b*128 + m] - mu;
        s2 = fmaf(d, d, s2);
    }
    g_mu[m]   = mu;
    g_rstd[m] = rsqrtf(s2 * (1.f/128.f) + BN_EPS);
}

// ---------------- K5: BN + activation + nonzero compaction --------------
__global__ void k_bnact(const float* __restrict__ gamma, const float* __restrict__ beta,
                        int l, int last)
{
    const int b = blockIdx.x;
    const int m = threadIdx.x;  // 128
    __shared__ int scnt;
    if (m == 0) scnt = 0;
    __syncthreads();

    float v = g_pre[b*128 + m];
    v = fmaf(gamma[l*128 + m] * (v - g_mu[m]), g_rstd[m], beta[l*128 + m]);
    if (!last) {
        v = fmaxf(v, 0.f);
    } else {
        // -1 + relu(v+0.5)/0.5 - relu(v-0.5)/0.5
        v = -1.f + fmaxf(v + 0.5f, 0.f)*2.f - fmaxf(v - 0.5f, 0.f)*2.f;
    }
    g_xe[b*128 + m] = v;
    if (v != 0.f) {
        int p = atomicAdd(&scnt, 1);
        g_nzidx[b*128 + p] = m;
    }
    __syncthreads();
    if (m == 0) g_nzcnt[b] = scnt;
}

// ---------------- K6: loss partials, pred = sum_{n in nz} x*B -----------
// grid (4 chunks, 128 b), 256 threads; each thread owns 8 (m,k) positions
__global__ void k_loss(const float* __restrict__ B, const float* __restrict__ z, int l)
{
    const int b   = blockIdx.y;
    const int ch  = blockIdx.x;
    const int tid = threadIdx.x;
    __shared__ float xs[128];
    __shared__ int   idxs[128];
    __shared__ int   scnt;
    __shared__ float wsum[8];

    if (tid < 128) {
        xs[tid]   = g_xe[b*128 + tid];
        idxs[tid] = g_nzidx[b*128 + tid];
    }
    if (tid == 0) scnt = g_nzcnt[b];
    __syncthreads();

    float a0=0,a1=0,a2=0,a3=0,a4=0,a5=0,a6=0,a7=0;
    const float4* Bb = reinterpret_cast<const float4*>(B) + (size_t)b*262144 + ch*512 + tid;
    const int cnt = scnt;

    int i = 0;
    for (; i + 2 <= cnt; i += 2) {
        int n0 = idxs[i], n1 = idxs[i+1];
        float x0 = xs[n0], x1 = xs[n1];
        const float4* p0 = Bb + (size_t)n0*2048;
        const float4* p1 = Bb + (size_t)n1*2048;
        float4 u0 = p0[0], u1 = p0[256];
        float4 v0 = p1[0], v1 = p1[256];
        a0=fmaf(x0,u0.x,a0); a1=fmaf(x0,u0.y,a1); a2=fmaf(x0,u0.z,a2); a3=fmaf(x0,u0.w,a3);
        a4=fmaf(x0,u1.x,a4); a5=fmaf(x0,u1.y,a5); a6=fmaf(x0,u1.z,a6); a7=fmaf(x0,u1.w,a7);
        a0=fmaf(x1,v0.x,a0); a1=fmaf(x1,v0.y,a1); a2=fmaf(x1,v0.z,a2); a3=fmaf(x1,v0.w,a3);
        a4=fmaf(x1,v1.x,a4); a5=fmaf(x1,v1.y,a5); a6=fmaf(x1,v1.z,a6); a7=fmaf(x1,v1.w,a7);
    }
    if (i < cnt) {
        int n0 = idxs[i];
        float x0 = xs[n0];
        const float4* p0 = Bb + (size_t)n0*2048;
        float4 u0 = p0[0], u1 = p0[256];
        a0=fmaf(x0,u0.x,a0); a1=fmaf(x0,u0.y,a1); a2=fmaf(x0,u0.z,a2); a3=fmaf(x0,u0.w,a3);
        a4=fmaf(x0,u1.x,a4); a5=fmaf(x0,u1.y,a5); a6=fmaf(x0,u1.z,a6); a7=fmaf(x0,u1.w,a7);
    }

    const float4* zp = reinterpret_cast<const float4*>(z) + (size_t)b*2048 + ch*512 + tid;
    float4 z0 = zp[0], z1 = zp[256];
    float part = 0.f, e;
    e = z0.x - a0; part = fmaf(e,e,part);
    e = z0.y - a1; part = fmaf(e,e,part);
    e = z0.z - a2; part = fmaf(e,e,part);
    e = z0.w - a3; part = fmaf(e,e,part);
    e = z1.x - a4; part = fmaf(e,e,part);
    e = z1.y - a5; part = fmaf(e,e,part);
    e = z1.z - a6; part = fmaf(e,e,part);
    e = z1.w - a7; part = fmaf(e,e,part);

#pragma unroll
    for (int o = 16; o > 0; o >>= 1)
        part += __shfl_down_sync(0xffffffffu, part, o);
    if ((tid & 31) == 0) wsum[tid >> 5] = part;
    __syncthreads();
    if (tid == 0) {
        float t = 0.f;
#pragma unroll
        for (int w = 0; w < 8; w++) t += wsum[w];
        g_part[l*512 + b*4 + ch] = t;
    }
}

// ---------------- K7: output x_est + losses -----------------------------
__global__ void k_copy(float* __restrict__ out)
{
    int i = blockIdx.x*256 + threadIdx.x;  // grid 64
    out[i] = g_xe[i];
}

__global__ void k_losses(float* __restrict__ out,
                         float s1, float s2, float s3, float s4, float s5)
{
    __shared__ float sm[256];
    const int t = threadIdx.x;  // 1 block, 256 threads
    const float scales[6] = {0.f, s1, s2, s3, s4, s5};
    if (t == 0) out[16384] = 0.f;
    for (int l = 1; l < 6; l++) {
        sm[t] = g_part[l*512 + t] + g_part[l*512 + 256 + t];
        __syncthreads();
        for (int s = 128; s > 0; s >>= 1) {
            if (t < s) sm[t] += sm[t + s];
            __syncthreads();
        }
        if (t == 0) out[16384 + l] = scales[l] * sm[0];
        __syncthreads();
    }
}

// ---------------- launch ------------------------------------------------
extern "C" void kernel_launch(void* const* d_in, const int* in_sizes, int n_in,
                              void* d_out, int out_size)
{
    (void)in_sizes; (void)n_in; (void)out_size;
    const float* BB    = (const float*)d_in[0];
    const float* zB    = (const float*)d_in[1];
    /* d_in[2] "x" is unused by the reference */
    const float* z     = (const float*)d_in[3];
    const float* B     = (const float*)d_in[4];
    const float* x0    = (const float*)d_in[5];
    const float* w_x   = (const float*)d_in[6];
    const float* wKL   = (const float*)d_in[7];
    const float* gamma = (const float*)d_in[8];
    const float* beta  = (const float*)d_in[9];
    float* out = (float*)d_out;

    k_buildC<<<dim3(4,128), 256>>>(BB, wKL);
    k_buildD<<<128, 128>>>(zB, wKL);

    for (int l = 0; l < 6; l++) {
        k_pre<<<128, 128>>>(x0, w_x, l, (l == 0) ? 1 : 0, (l > 0) ? 1 : 0);
        k_stats<<<1, 128>>>();
        k_bnact<<<128, 128>>>(gamma, beta, l, (l == 5) ? 1 : 0);
        if (l > 0)  // losses[0] == 0 exactly (SCALAR*ln(1)=0): skip B pass
            k_loss<<<dim3(4,128), 256>>>(B, z, l);
    }

    const float inv = 1.0f / 16384.0f;  // mean over (batch, N)
    k_copy<<<64, 256>>>(out);
    k_losses<<<1, 256>>>(out,
        10.0f * logf(2.0f) * inv,
        10.0f * logf(3.0f) * inv,
        10.0f * logf(4.0f) * inv,
        10.0f * logf(5.0f) * inv,
        10.0f * logf(6.0f) * inv);
}

// round 2
// speedup vs baseline: 1.1152x; 1.1152x over previous
#include <cuda_runtime.h>
#include <math.h>

#define BN_EPS 1e-5f

// ---------------- device scratch (static; no allocation) ----------------
__device__ float g_C[(size_t)6*128*128*128];   // [l][b][n][m]  48 MB
__device__ float g_d[6*128*128];               // [l][b][m]
__device__ float g_pre[128*128];               // out_x before BN (current layer)
__device__ float g_xe[128*128];                // current x_est
__device__ float g_mu[128];
__device__ float g_rstd[128];
__device__ int   g_nzidx[128*128];
__device__ int   g_nzcnt[128];
__device__ float g_part[6*512];                // per-block loss partials

// ---------------- K1: C_l[b,n,m] = sum_k BB[b,n,m,k]*wKL[l,k,m] ---------
// grid (4 m-tiles, 128 b), 256 threads = 32 m x 8 k-groups
__global__ void k_buildC(const float* __restrict__ BB, const float* __restrict__ wKL)
{
    const int m0   = blockIdx.x * 32;
    const int b    = blockIdx.y;
    const int mloc = threadIdx.x >> 3;   // 0..31
    const int tk   = threadIdx.x & 7;    // 0..7
    const int m    = m0 + mloc;

    float w[6][8];
#pragma unroll
    for (int l = 0; l < 6; l++)
#pragma unroll
        for (int kk = 0; kk < 8; kk++)
            w[l][kk] = wKL[(l*64 + tk*8 + kk)*128 + m];

    const float4* BB4 = reinterpret_cast<const float4*>(BB);
    const size_t off0 = (size_t)b*262144 + (size_t)m*16 + tk*2;

    for (int n = 0; n < 128; n += 2) {
        const float4* p  = BB4 + off0 + (size_t)n*2048;
        const float4* q  = p + 2048;
        float4 v0 = p[0], v1 = p[1];
        float4 u0 = q[0], u1 = q[1];
        float vv[8] = {v0.x, v0.y, v0.z, v0.w, v1.x, v1.y, v1.z, v1.w};
        float uu[8] = {u0.x, u0.y, u0.z, u0.w, u1.x, u1.y, u1.z, u1.w};
        float acc[6] = {0,0,0,0,0,0};
        float bcc[6] = {0,0,0,0,0,0};
#pragma unroll
        for (int kk = 0; kk < 8; kk++) {
            float xv = vv[kk], xu = uu[kk];
#pragma unroll
            for (int l = 0; l < 6; l++) {
                acc[l] = fmaf(xv, w[l][kk], acc[l]);
                bcc[l] = fmaf(xu, w[l][kk], bcc[l]);
            }
        }
#pragma unroll
        for (int l = 0; l < 6; l++) {
            float a = acc[l], c = bcc[l];
            a += __shfl_down_sync(0xffffffffu, a, 4, 8);
            c += __shfl_down_sync(0xffffffffu, c, 4, 8);
            a += __shfl_down_sync(0xffffffffu, a, 2, 8);
            c += __shfl_down_sync(0xffffffffu, c, 2, 8);
            a += __shfl_down_sync(0xffffffffu, a, 1, 8);
            c += __shfl_down_sync(0xffffffffu, c, 1, 8);
            if (tk == 0) {
                g_C[(((size_t)l*128 + b)*128 + n  )*128 + m] = a;
                g_C[(((size_t)l*128 + b)*128 + n+1)*128 + m] = c;
            }
        }
    }
}

// ---------------- K2: d_l[b,m] = sum_k zB[b,m,k]*wKL[l,k,m] -------------
__global__ void k_buildD(const float* __restrict__ zB, const float* __restrict__ wKL)
{
    const int b = blockIdx.x;
    const int m = threadIdx.x;  // 128 threads
    __shared__ float s[128*65];
    const float* src = zB + (size_t)b*8192;
    for (int i = m; i < 8192; i += 128)
        s[(i >> 6)*65 + (i & 63)] = src[i];
    __syncthreads();
#pragma unroll
    for (int l = 0; l < 6; l++) {
        float acc = 0.f;
#pragma unroll
        for (int k = 0; k < 64; k++)
            acc = fmaf(s[m*65 + k], wKL[(l*64 + k)*128 + m], acc);
        g_d[(l*128 + b)*128 + m] = acc;
    }
}

// ---------------- K3: layer-0 pre from x0 (dense) -----------------------
__global__ void k_pre0(const float* __restrict__ xin, const float* __restrict__ wx)
{
    const int b = blockIdx.x;
    const int m = threadIdx.x;  // 128
    __shared__ float xs[128];
    float xv = xin[b*128 + m];
    xs[m] = xv;
    __syncthreads();
    float acc = fmaf(xv, wx[m], -g_d[b*128 + m]);
    const float* Cb = g_C + (size_t)b*16384;
#pragma unroll 4
    for (int n = 0; n < 128; n++)
        acc = fmaf(xs[n], Cb[n*128 + m], acc);
    g_pre[b*128 + m] = acc;
}

// ---------------- K4: batch stats, 1 block x 1024, single pass ----------
__global__ void k_stats()
{
    const int t = threadIdx.x;
    const int m = t & 127;
    const int g = t >> 7;        // 0..7
    float s = 0.f, s2 = 0.f;
#pragma unroll
    for (int b = g; b < 128; b += 8) {
        float v = g_pre[b*128 + m];
        s += v;
        s2 = fmaf(v, v, s2);
    }
    __shared__ float ss[8][128], sq[8][128];
    ss[g][m] = s; sq[g][m] = s2;
    __syncthreads();
    if (g == 0) {
        float a = 0.f, a2 = 0.f;
#pragma unroll
        for (int i = 0; i < 8; i++) { a += ss[i][m]; a2 += sq[i][m]; }
        float mu = a * (1.f/128.f);
        float var = fmaf(-mu, mu, a2 * (1.f/128.f));
        g_mu[m]   = mu;
        g_rstd[m] = rsqrtf(var + BN_EPS);
    }
}

// ---------------- K5: fused BN+act+compaction (+ next-layer pre) --------
// grid 128 (b), 128 threads (m). gamma/beta index l; wx/d/C index l+1.
__global__ void k_fused(const float* __restrict__ gamma, const float* __restrict__ beta,
                        const float* __restrict__ wx, int l)
{
    const int b = blockIdx.x;
    const int m = threadIdx.x;
    const int lane = m & 31, w = m >> 5;
    const int last = (l == 5);
    __shared__ float xs[128];
    __shared__ int   idxs[128];
    __shared__ int   wcnt[4];

    float v = g_pre[b*128 + m];
    v = fmaf(gamma[l*128 + m] * (v - g_mu[m]), g_rstd[m], beta[l*128 + m]);
    if (!last)
        v = fmaxf(v, 0.f);
    else
        v = -1.f + fmaxf(v + 0.5f, 0.f)*2.f - fmaxf(v - 0.5f, 0.f)*2.f;
    g_xe[b*128 + m] = v;
    xs[m] = v;

    unsigned mask = __ballot_sync(0xffffffffu, v != 0.f);
    if (lane == 0) wcnt[w] = __popc(mask);
    __syncthreads();
    int base = 0;
#pragma unroll
    for (int i = 0; i < 4; i++) { if (i < w) base += wcnt[i]; }
    const int cnt = wcnt[0] + wcnt[1] + wcnt[2] + wcnt[3];
    if (v != 0.f) {
        int p = base + __popc(mask & ((1u << lane) - 1u));
        idxs[p] = m;
        g_nzidx[b*128 + p] = m;
    }
    if (m == 0) g_nzcnt[b] = cnt;
    __syncthreads();

    if (last) return;

    // next-layer pre for this b
    const int ln = l + 1;
    float acc = fmaf(v, wx[ln*128 + m], -g_d[(ln*128 + b)*128 + m]);
    const float* Cb = g_C + ((size_t)ln*128 + b)*16384;
    int i = 0;
    for (; i + 4 <= cnt; i += 4) {
        int n0 = idxs[i], n1 = idxs[i+1], n2 = idxs[i+2], n3 = idxs[i+3];
        float c0 = Cb[n0*128 + m], c1 = Cb[n1*128 + m];
        float c2 = Cb[n2*128 + m], c3 = Cb[n3*128 + m];
        acc = fmaf(xs[n0], c0, acc);
        acc = fmaf(xs[n1], c1, acc);
        acc = fmaf(xs[n2], c2, acc);
        acc = fmaf(xs[n3], c3, acc);
    }
    for (; i < cnt; i++) {
        int n = idxs[i];
        acc = fmaf(xs[n], Cb[n*128 + m], acc);
    }
    g_pre[b*128 + m] = acc;
}

// ---------------- K6: loss partials, pred = sum_{n in nz} x*B -----------
__global__ void k_loss(const float* __restrict__ B, const float* __restrict__ z, int l)
{
    const int b   = blockIdx.y;
    const int ch  = blockIdx.x;
    const int tid = threadIdx.x;
    __shared__ float xs[128];
    __shared__ int   idxs[128];
    __shared__ int   scnt;
    __shared__ float wsum[8];

    if (tid < 128) {
        xs[tid]   = g_xe[b*128 + tid];
        idxs[tid] = g_nzidx[b*128 + tid];
    }
    if (tid == 0) scnt = g_nzcnt[b];
    __syncthreads();

    float a0=0,a1=0,a2=0,a3=0,a4=0,a5=0,a6=0,a7=0;
    const float4* Bb = reinterpret_cast<const float4*>(B) + (size_t)b*262144 + ch*512 + tid;
    const int cnt = scnt;

    int i = 0;
    for (; i + 2 <= cnt; i += 2) {
        int n0 = idxs[i], n1 = idxs[i+1];
        float x0 = xs[n0], x1 = xs[n1];
        const float4* p0 = Bb + (size_t)n0*2048;
        const float4* p1 = Bb + (size_t)n1*2048;
        float4 u0 = p0[0], u1 = p0[256];
        float4 v0 = p1[0], v1 = p1[256];
        a0=fmaf(x0,u0.x,a0); a1=fmaf(x0,u0.y,a1); a2=fmaf(x0,u0.z,a2); a3=fmaf(x0,u0.w,a3);
        a4=fmaf(x0,u1.x,a4); a5=fmaf(x0,u1.y,a5); a6=fmaf(x0,u1.z,a6); a7=fmaf(x0,u1.w,a7);
        a0=fmaf(x1,v0.x,a0); a1=fmaf(x1,v0.y,a1); a2=fmaf(x1,v0.z,a2); a3=fmaf(x1,v0.w,a3);
        a4=fmaf(x1,v1.x,a4); a5=fmaf(x1,v1.y,a5); a6=fmaf(x1,v1.z,a6); a7=fmaf(x1,v1.w,a7);
    }
    if (i < cnt) {
        int n0 = idxs[i];
        float x0 = xs[n0];
        const float4* p0 = Bb + (size_t)n0*2048;
        float4 u0 = p0[0], u1 = p0[256];
        a0=fmaf(x0,u0.x,a0); a1=fmaf(x0,u0.y,a1); a2=fmaf(x0,u0.z,a2); a3=fmaf(x0,u0.w,a3);
        a4=fmaf(x0,u1.x,a4); a5=fmaf(x0,u1.y,a5); a6=fmaf(x0,u1.z,a6); a7=fmaf(x0,u1.w,a7);
    }

    const float4* zp = reinterpret_cast<const float4*>(z) + (size_t)b*2048 + ch*512 + tid;
    float4 z0 = zp[0], z1 = zp[256];
    float part = 0.f, e;
    e = z0.x - a0; part = fmaf(e,e,part);
    e = z0.y - a1; part = fmaf(e,e,part);
    e = z0.z - a2; part = fmaf(e,e,part);
    e = z0.w - a3; part = fmaf(e,e,part);
    e = z1.x - a4; part = fmaf(e,e,part);
    e = z1.y - a5; part = fmaf(e,e,part);
    e = z1.z - a6; part = fmaf(e,e,part);
    e = z1.w - a7; part = fmaf(e,e,part);

#pragma unroll
    for (int o = 16; o > 0; o >>= 1)
        part += __shfl_down_sync(0xffffffffu, part, o);
    if ((tid & 31) == 0) wsum[tid >> 5] = part;
    __syncthreads();
    if (tid == 0) {
        float t = 0.f;
#pragma unroll
        for (int w = 0; w < 8; w++) t += wsum[w];
        g_part[l*512 + b*4 + ch] = t;
    }
}

// ---------------- K7: output x_est + losses -----------------------------
__global__ void k_copy(float* __restrict__ out)
{
    int i = blockIdx.x*256 + threadIdx.x;  // grid 64
    out[i] = g_xe[i];
}

__global__ void k_losses(float* __restrict__ out,
                         float s1, float s2, float s3, float s4, float s5)
{
    __shared__ float sm[256];
    const int t = threadIdx.x;  // 1 block, 256 threads
    const float scales[6] = {0.f, s1, s2, s3, s4, s5};
    if (t == 0) out[16384] = 0.f;
    for (int l = 1; l < 6; l++) {
        sm[t] = g_part[l*512 + t] + g_part[l*512 + 256 + t];
        __syncthreads();
        for (int s = 128; s > 0; s >>= 1) {
            if (t < s) sm[t] += sm[t + s];
            __syncthreads();
        }
        if (t == 0) out[16384 + l] = scales[l] * sm[0];
        __syncthreads();
    }
}

// ---------------- launch ------------------------------------------------
extern "C" void kernel_launch(void* const* d_in, const int* in_sizes, int n_in,
                              void* d_out, int out_size)
{
    (void)in_sizes; (void)n_in; (void)out_size;
    const float* BB    = (const float*)d_in[0];
    const float* zB    = (const float*)d_in[1];
    const float* z     = (const float*)d_in[3];
    const float* B     = (const float*)d_in[4];
    const float* x0    = (const float*)d_in[5];
    const float* w_x   = (const float*)d_in[6];
    const float* wKL   = (const float*)d_in[7];
    const float* gamma = (const float*)d_in[8];
    const float* beta  = (const float*)d_in[9];
    float* out = (float*)d_out;

    k_buildC<<<dim3(4,128), 256>>>(BB, wKL);
    k_buildD<<<128, 128>>>(zB, wKL);
    k_pre0<<<128, 128>>>(x0, w_x);

    for (int l = 0; l < 6; l++) {
        k_stats<<<1, 1024>>>();
        k_fused<<<128, 128>>>(gamma, beta, w_x, l);
        if (l > 0)  // losses[0] == 0 exactly
            k_loss<<<dim3(4,128), 256>>>(B, z, l);
    }

    const float inv = 1.0f / 16384.0f;
    k_copy<<<64, 256>>>(out);
    k_losses<<<1, 256>>>(out,
        10.0f * logf(2.0f) * inv,
        10.0f * logf(3.0f) * inv,
        10.0f * logf(4.0f) * inv,
        10.0f * logf(5.0f) * inv,
        10.0f * logf(6.0f) * inv);
}

// round 3
// speedup vs baseline: 1.6187x; 1.4515x over previous
#include <cuda_runtime.h>
#include <math.h>

#define BN_EPS 1e-5f

// ---------------- device scratch (static; no allocation) ----------------
__device__ float g_C[(size_t)6*128*128*128];   // [l][b][n][m]  48 MB
__device__ float g_d[6*128*128];               // [l][b][m]
__device__ float g_pre[128*128];               // out_x before BN (current layer)
__device__ float g_xeL[6*128*128];             // x_est per layer [l][b][m]
__device__ float g_mu[128];
__device__ float g_rstd[128];
__device__ float g_part[6*512];                // per-block loss partials

// ---------------- K1: C_l[b,n,m] = sum_k BB[b,n,m,k]*wKL[l,k,m] ---------
// grid (4 m-tiles, 128 b), 256 threads = 32 m x 8 k-groups
__global__ void k_buildC(const float* __restrict__ BB, const float* __restrict__ wKL)
{
    const int m0   = blockIdx.x * 32;
    const int b    = blockIdx.y;
    const int mloc = threadIdx.x >> 3;   // 0..31
    const int tk   = threadIdx.x & 7;    // 0..7
    const int m    = m0 + mloc;

    float w[6][8];
#pragma unroll
    for (int l = 0; l < 6; l++)
#pragma unroll
        for (int kk = 0; kk < 8; kk++)
            w[l][kk] = wKL[(l*64 + tk*8 + kk)*128 + m];

    const float4* BB4 = reinterpret_cast<const float4*>(BB);
    const size_t off0 = (size_t)b*262144 + (size_t)m*16 + tk*2;

    for (int n = 0; n < 128; n += 2) {
        const float4* p  = BB4 + off0 + (size_t)n*2048;
        const float4* q  = p + 2048;
        float4 v0 = p[0], v1 = p[1];
        float4 u0 = q[0], u1 = q[1];
        float vv[8] = {v0.x, v0.y, v0.z, v0.w, v1.x, v1.y, v1.z, v1.w};
        float uu[8] = {u0.x, u0.y, u0.z, u0.w, u1.x, u1.y, u1.z, u1.w};
        float acc[6] = {0,0,0,0,0,0};
        float bcc[6] = {0,0,0,0,0,0};
#pragma unroll
        for (int kk = 0; kk < 8; kk++) {
            float xv = vv[kk], xu = uu[kk];
#pragma unroll
            for (int l = 0; l < 6; l++) {
                acc[l] = fmaf(xv, w[l][kk], acc[l]);
                bcc[l] = fmaf(xu, w[l][kk], bcc[l]);
            }
        }
#pragma unroll
        for (int l = 0; l < 6; l++) {
            float a = acc[l], c = bcc[l];
            a += __shfl_down_sync(0xffffffffu, a, 4, 8);
            c += __shfl_down_sync(0xffffffffu, c, 4, 8);
            a += __shfl_down_sync(0xffffffffu, a, 2, 8);
            c += __shfl_down_sync(0xffffffffu, c, 2, 8);
            a += __shfl_down_sync(0xffffffffu, a, 1, 8);
            c += __shfl_down_sync(0xffffffffu, c, 1, 8);
            if (tk == 0) {
                g_C[(((size_t)l*128 + b)*128 + n  )*128 + m] = a;
                g_C[(((size_t)l*128 + b)*128 + n+1)*128 + m] = c;
            }
        }
    }
}

// ---------------- K2: d_l[b,m] = sum_k zB[b,m,k]*wKL[l,k,m] -------------
__global__ void k_buildD(const float* __restrict__ zB, const float* __restrict__ wKL)
{
    const int b = blockIdx.x;
    const int m = threadIdx.x;  // 128 threads
    __shared__ float s[128*65];
    const float* src = zB + (size_t)b*8192;
    for (int i = m; i < 8192; i += 128)
        s[(i >> 6)*65 + (i & 63)] = src[i];
    __syncthreads();
#pragma unroll
    for (int l = 0; l < 6; l++) {
        float acc = 0.f;
#pragma unroll
        for (int k = 0; k < 64; k++)
            acc = fmaf(s[m*65 + k], wKL[(l*64 + k)*128 + m], acc);
        g_d[(l*128 + b)*128 + m] = acc;
    }
}

// ---------------- K3: layer-0 pre from x0 (dense) -----------------------
__global__ void k_pre0(const float* __restrict__ xin, const float* __restrict__ wx)
{
    const int b = blockIdx.x;
    const int m = threadIdx.x;  // 128
    __shared__ float xs[128];
    float xv = xin[b*128 + m];
    xs[m] = xv;
    __syncthreads();
    float acc = fmaf(xv, wx[m], -g_d[b*128 + m]);
    const float* Cb = g_C + (size_t)b*16384;
#pragma unroll 4
    for (int n = 0; n < 128; n++)
        acc = fmaf(xs[n], Cb[n*128 + m], acc);
    g_pre[b*128 + m] = acc;
}

// ---------------- K4: batch stats, 1 block x 1024, single pass ----------
__global__ void k_stats()
{
    const int t = threadIdx.x;
    const int m = t & 127;
    const int g = t >> 7;        // 0..7
    float s = 0.f, s2 = 0.f;
#pragma unroll
    for (int b = g; b < 128; b += 8) {
        float v = g_pre[b*128 + m];
        s += v;
        s2 = fmaf(v, v, s2);
    }
    __shared__ float ss[8][128], sq[8][128];
    ss[g][m] = s; sq[g][m] = s2;
    __syncthreads();
    if (g == 0) {
        float a = 0.f, a2 = 0.f;
#pragma unroll
        for (int i = 0; i < 8; i++) { a += ss[i][m]; a2 += sq[i][m]; }
        float mu = a * (1.f/128.f);
        float var = fmaf(-mu, mu, a2 * (1.f/128.f));
        g_mu[m]   = mu;
        g_rstd[m] = rsqrtf(var + BN_EPS);
    }
}

// ---------------- K5: fused BN+act (+ next-layer pre via nz gather) -----
// grid 128 (b), 128 threads (m). gamma/beta index l; wx/d/C index l+1.
__global__ void k_fused(const float* __restrict__ gamma, const float* __restrict__ beta,
                        const float* __restrict__ wx, int l)
{
    const int b = blockIdx.x;
    const int m = threadIdx.x;
    const int lane = m & 31, w = m >> 5;
    const int last = (l == 5);
    __shared__ float xs[128];
    __shared__ int   idxs[128];
    __shared__ int   wcnt[4];

    float v = g_pre[b*128 + m];
    v = fmaf(gamma[l*128 + m] * (v - g_mu[m]), g_rstd[m], beta[l*128 + m]);
    if (!last)
        v = fmaxf(v, 0.f);
    else
        v = -1.f + fmaxf(v + 0.5f, 0.f)*2.f - fmaxf(v - 0.5f, 0.f)*2.f;
    g_xeL[l*16384 + b*128 + m] = v;
    xs[m] = v;

    if (last) return;

    unsigned mask = __ballot_sync(0xffffffffu, v != 0.f);
    if (lane == 0) wcnt[w] = __popc(mask);
    __syncthreads();
    int base = 0;
#pragma unroll
    for (int i = 0; i < 4; i++) { if (i < w) base += wcnt[i]; }
    const int cnt = wcnt[0] + wcnt[1] + wcnt[2] + wcnt[3];
    if (v != 0.f) {
        int p = base + __popc(mask & ((1u << lane) - 1u));
        idxs[p] = m;
    }
    __syncthreads();

    // next-layer pre for this b (gather only nonzero rows of C)
    const int ln = l + 1;
    float acc = fmaf(v, wx[ln*128 + m], -g_d[(ln*128 + b)*128 + m]);
    const float* Cb = g_C + ((size_t)ln*128 + b)*16384;
    int i = 0;
    for (; i + 4 <= cnt; i += 4) {
        int n0 = idxs[i], n1 = idxs[i+1], n2 = idxs[i+2], n3 = idxs[i+3];
        float c0 = Cb[n0*128 + m], c1 = Cb[n1*128 + m];
        float c2 = Cb[n2*128 + m], c3 = Cb[n3*128 + m];
        acc = fmaf(xs[n0], c0, acc);
        acc = fmaf(xs[n1], c1, acc);
        acc = fmaf(xs[n2], c2, acc);
        acc = fmaf(xs[n3], c3, acc);
    }
    for (; i < cnt; i++) {
        int n = idxs[i];
        acc = fmaf(xs[n], Cb[n*128 + m], acc);
    }
    g_pre[b*128 + m] = acc;
}

// ---------------- K6: ALL-layer loss partials in ONE pass over B --------
// grid (4 chunks, 128 b), 256 threads; each thread owns 8 (m,k) positions;
// for every loaded B element: 5 FMAs (layers 1..5).
__global__ void k_loss_all(const float* __restrict__ B, const float* __restrict__ z)
{
    const int b   = blockIdx.y;
    const int ch  = blockIdx.x;
    const int tid = threadIdx.x;
    __shared__ float xs[5*128];
    __shared__ float wsum[5][8];

    if (tid < 128) {
#pragma unroll
        for (int l = 0; l < 5; l++)
            xs[l*128 + tid] = g_xeL[(l+1)*16384 + b*128 + tid];
    }
    __syncthreads();

    float acc[5][8];
#pragma unroll
    for (int l = 0; l < 5; l++)
#pragma unroll
        for (int j = 0; j < 8; j++) acc[l][j] = 0.f;

    const float4* Bb = reinterpret_cast<const float4*>(B) + (size_t)b*262144 + ch*512 + tid;

    for (int n = 0; n < 128; n += 2) {
        const float4* p0 = Bb + (size_t)n*2048;
        const float4* p1 = p0 + 2048;
        float4 u0 = p0[0], u1 = p0[256];
        float4 v0 = p1[0], v1 = p1[256];
        float uu[8] = {u0.x,u0.y,u0.z,u0.w,u1.x,u1.y,u1.z,u1.w};
        float vv[8] = {v0.x,v0.y,v0.z,v0.w,v1.x,v1.y,v1.z,v1.w};
#pragma unroll
        for (int l = 0; l < 5; l++) {
            float x0 = xs[l*128 + n];
            float x1 = xs[l*128 + n + 1];
#pragma unroll
            for (int j = 0; j < 8; j++) {
                acc[l][j] = fmaf(x0, uu[j], acc[l][j]);
                acc[l][j] = fmaf(x1, vv[j], acc[l][j]);
            }
        }
    }

    const float4* zp = reinterpret_cast<const float4*>(z) + (size_t)b*2048 + ch*512 + tid;
    float4 z0 = zp[0], z1 = zp[256];
    float zz[8] = {z0.x,z0.y,z0.z,z0.w,z1.x,z1.y,z1.z,z1.w};

#pragma unroll
    for (int l = 0; l < 5; l++) {
        float part = 0.f;
#pragma unroll
        for (int j = 0; j < 8; j++) {
            float e = zz[j] - acc[l][j];
            part = fmaf(e, e, part);
        }
#pragma unroll
        for (int o = 16; o > 0; o >>= 1)
            part += __shfl_down_sync(0xffffffffu, part, o);
        if ((tid & 31) == 0) wsum[l][tid >> 5] = part;
    }
    __syncthreads();
    if (tid == 0) {
#pragma unroll
        for (int l = 0; l < 5; l++) {
            float t = 0.f;
#pragma unroll
            for (int w = 0; w < 8; w++) t += wsum[l][w];
            g_part[(l+1)*512 + b*4 + ch] = t;
        }
    }
}

// ---------------- K7: output x_est + losses -----------------------------
__global__ void k_copy(float* __restrict__ out)
{
    int i = blockIdx.x*256 + threadIdx.x;  // grid 64
    out[i] = g_xeL[5*16384 + i];
}

__global__ void k_losses(float* __restrict__ out,
                         float s1, float s2, float s3, float s4, float s5)
{
    __shared__ float sm[256];
    const int t = threadIdx.x;  // 1 block, 256 threads
    const float scales[6] = {0.f, s1, s2, s3, s4, s5};
    if (t == 0) out[16384] = 0.f;
    for (int l = 1; l < 6; l++) {
        sm[t] = g_part[l*512 + t] + g_part[l*512 + 256 + t];
        __syncthreads();
        for (int s = 128; s > 0; s >>= 1) {
            if (t < s) sm[t] += sm[t + s];
            __syncthreads();
        }
        if (t == 0) out[16384 + l] = scales[l] * sm[0];
        __syncthreads();
    }
}

// ---------------- launch ------------------------------------------------
extern "C" void kernel_launch(void* const* d_in, const int* in_sizes, int n_in,
                              void* d_out, int out_size)
{
    (void)in_sizes; (void)n_in; (void)out_size;
    const float* BB    = (const float*)d_in[0];
    const float* zB    = (const float*)d_in[1];
    const float* z     = (const float*)d_in[3];
    const float* B     = (const float*)d_in[4];
    const float* x0    = (const float*)d_in[5];
    const float* w_x   = (const float*)d_in[6];
    const float* wKL   = (const float*)d_in[7];
    const float* gamma = (const float*)d_in[8];
    const float* beta  = (const float*)d_in[9];
    float* out = (float*)d_out;

    k_buildC<<<dim3(4,128), 256>>>(BB, wKL);
    k_buildD<<<128, 128>>>(zB, wKL);
    k_pre0<<<128, 128>>>(x0, w_x);

    for (int l = 0; l < 6; l++) {
        k_stats<<<1, 1024>>>();
        k_fused<<<128, 128>>>(gamma, beta, w_x, l);
    }

    // one dense pass over B computes all 5 nonzero losses
    k_loss_all<<<dim3(4,128), 256>>>(B, z);

    const float inv = 1.0f / 16384.0f;
    k_copy<<<64, 256>>>(out);
    k_losses<<<1, 256>>>(out,
        10.0f * logf(2.0f) * inv,
        10.0f * logf(3.0f) * inv,
        10.0f * logf(4.0f) * inv,
        10.0f * logf(5.0f) * inv,
        10.0f * logf(6.0f) * inv);
}

// round 5
// speedup vs baseline: 1.6438x; 1.0155x over previous
#include <cuda_runtime.h>
#include <math.h>

#define BN_EPS 1e-5f

// ---------------- device scratch (static; no allocation) ----------------
__device__ float g_C[(size_t)6*128*128*128];   // [l][b][n][m]  48 MB
__device__ float g_d[6*128*128];               // [l][b][m]
__device__ float g_pre[128*128];               // out_x before BN (current layer)
__device__ float g_xeL[6*128*128];             // x_est per layer [l][b][m]
__device__ float g_mu[128];
__device__ float g_rstd[128];
__device__ float g_part[6*512];                // per-block loss partials
__device__ unsigned g_bar_cnt = 0;
__device__ volatile unsigned g_bar_gen = 0;

// ---------------- grid barrier (128 co-resident blocks) -----------------
__device__ __forceinline__ void gridbar(int nblocks)
{
    __syncthreads();
    if (threadIdx.x == 0) {
        __threadfence();
        unsigned gen = g_bar_gen;
        if (atomicAdd(&g_bar_cnt, 1u) == (unsigned)(nblocks - 1)) {
            g_bar_cnt = 0;
            __threadfence();
            g_bar_gen = gen + 1u;
        } else {
            while (g_bar_gen == gen) __nanosleep(32);
        }
        __threadfence();
    }
    __syncthreads();
}

// ---------------- K1: C_l[b,n,m] = sum_k BB[b,n,m,k]*wKL[l,k,m] ---------
// grid (4 m-tiles, 128 b), 256 threads = 32 m x 8 k-groups
__global__ void k_buildC(const float* __restrict__ BB, const float* __restrict__ wKL)
{
    const int m0   = blockIdx.x * 32;
    const int b    = blockIdx.y;
    const int mloc = threadIdx.x >> 3;   // 0..31
    const int tk   = threadIdx.x & 7;    // 0..7
    const int m    = m0 + mloc;

    float w[6][8];
#pragma unroll
    for (int l = 0; l < 6; l++)
#pragma unroll
        for (int kk = 0; kk < 8; kk++)
            w[l][kk] = wKL[(l*64 + tk*8 + kk)*128 + m];

    const float4* BB4 = reinterpret_cast<const float4*>(BB);
    const size_t off0 = (size_t)b*262144 + (size_t)m*16 + tk*2;

    for (int n = 0; n < 128; n += 2) {
        const float4* p  = BB4 + off0 + (size_t)n*2048;
        const float4* q  = p + 2048;
        float4 v0 = p[0], v1 = p[1];
        float4 u0 = q[0], u1 = q[1];
        float vv[8] = {v0.x, v0.y, v0.z, v0.w, v1.x, v1.y, v1.z, v1.w};
        float uu[8] = {u0.x, u0.y, u0.z, u0.w, u1.x, u1.y, u1.z, u1.w};
        float acc[6] = {0,0,0,0,0,0};
        float bcc[6] = {0,0,0,0,0,0};
#pragma unroll
        for (int kk = 0; kk < 8; kk++) {
            float xv = vv[kk], xu = uu[kk];
#pragma unroll
            for (int l = 0; l < 6; l++) {
                acc[l] = fmaf(xv, w[l][kk], acc[l]);
                bcc[l] = fmaf(xu, w[l][kk], bcc[l]);
            }
        }
#pragma unroll
        for (int l = 0; l < 6; l++) {
            float a = acc[l], c = bcc[l];
            a += __shfl_down_sync(0xffffffffu, a, 4, 8);
            c += __shfl_down_sync(0xffffffffu, c, 4, 8);
            a += __shfl_down_sync(0xffffffffu, a, 2, 8);
            c += __shfl_down_sync(0xffffffffu, c, 2, 8);
            a += __shfl_down_sync(0xffffffffu, a, 1, 8);
            c += __shfl_down_sync(0xffffffffu, c, 1, 8);
            if (tk == 0) {
                g_C[(((size_t)l*128 + b)*128 + n  )*128 + m] = a;
                g_C[(((size_t)l*128 + b)*128 + n+1)*128 + m] = c;
            }
        }
    }
}

// ---------------- K2: d_l[b,m] = sum_k zB[b,m,k]*wKL[l,k,m] -------------
__global__ void k_buildD(const float* __restrict__ zB, const float* __restrict__ wKL)
{
    const int b = blockIdx.x;
    const int m = threadIdx.x;  // 128 threads
    __shared__ float s[128*65];
    const float* src = zB + (size_t)b*8192;
    for (int i = m; i < 8192; i += 128)
        s[(i >> 6)*65 + (i & 63)] = src[i];
    __syncthreads();
#pragma unroll
    for (int l = 0; l < 6; l++) {
        float acc = 0.f;
#pragma unroll
        for (int k = 0; k < 64; k++)
            acc = fmaf(s[m*65 + k], wKL[(l*64 + k)*128 + m], acc);
        g_d[(l*128 + b)*128 + m] = acc;
    }
}

// ---------------- K3: persistent layer chain ----------------------------
// grid 128 (one block per b, also one block per feature for stats phases)
__global__ void __launch_bounds__(128, 1)
k_chain(const float* __restrict__ x0, const float* __restrict__ wx,
        const float* __restrict__ gamma, const float* __restrict__ beta,
        float* __restrict__ out)
{
    const int b = blockIdx.x;
    const int m = threadIdx.x;
    const int lane = m & 31, w = m >> 5;
    __shared__ float xs[128];
    __shared__ int   idxs[128];
    __shared__ int   wcnt[4];
    __shared__ float rs[4], rq[4];

    // ---- layer-0 pre (dense) ----
    {
        float xv = x0[b*128 + m];
        xs[m] = xv;
        __syncthreads();
        float acc = fmaf(xv, wx[m], -g_d[b*128 + m]);
        const float* Cb = g_C + (size_t)b*16384;
#pragma unroll 4
        for (int n = 0; n < 128; n++)
            acc = fmaf(xs[n], Cb[n*128 + m], acc);
        g_pre[b*128 + m] = acc;
    }
    gridbar(128);

    for (int l = 0; l < 6; l++) {
        // ---- stats: this block owns feature j=b; threads cover batch ----
        {
            float v = g_pre[m*128 + b];
            float s = v, s2 = v*v;
#pragma unroll
            for (int o = 16; o > 0; o >>= 1) {
                s  += __shfl_down_sync(0xffffffffu, s,  o);
                s2 += __shfl_down_sync(0xffffffffu, s2, o);
            }
            if (lane == 0) { rs[w] = s; rq[w] = s2; }
            __syncthreads();
            if (m == 0) {
                float a  = rs[0]+rs[1]+rs[2]+rs[3];
                float a2 = rq[0]+rq[1]+rq[2]+rq[3];
                float mu  = a * (1.f/128.f);
                float var = fmaf(-mu, mu, a2 * (1.f/128.f));
                g_mu[b]   = mu;
                g_rstd[b] = rsqrtf(var + BN_EPS);
            }
        }
        gridbar(128);

        // ---- BN + activation for this b ----
        float v = g_pre[b*128 + m];
        v = fmaf(gamma[l*128 + m] * (v - g_mu[m]), g_rstd[m], beta[l*128 + m]);
        if (l < 5)
            v = fmaxf(v, 0.f);
        else
            v = -1.f + fmaxf(v + 0.5f, 0.f)*2.f - fmaxf(v - 0.5f, 0.f)*2.f;
        g_xeL[l*16384 + b*128 + m] = v;

        if (l == 5) {
            out[b*128 + m] = v;
            break;
        }

        // ---- compaction + next-layer pre ----
        __syncthreads();          // xs reuse
        xs[m] = v;
        unsigned mask = __ballot_sync(0xffffffffu, v != 0.f);
        if (lane == 0) wcnt[w] = __popc(mask);
        __syncthreads();
        int base = 0;
#pragma unroll
        for (int i = 0; i < 4; i++) { if (i < w) base += wcnt[i]; }
        const int cnt = wcnt[0] + wcnt[1] + wcnt[2] + wcnt[3];
        if (v != 0.f) {
            int p = base + __popc(mask & ((1u << lane) - 1u));
            idxs[p] = m;
        }
        __syncthreads();

        const int ln = l + 1;
        float acc = fmaf(v, wx[ln*128 + m], -g_d[(ln*128 + b)*128 + m]);
        const float* Cb = g_C + ((size_t)ln*128 + b)*16384;
        int i = 0;
        for (; i + 4 <= cnt; i += 4) {
            int n0 = idxs[i], n1 = idxs[i+1], n2 = idxs[i+2], n3 = idxs[i+3];
            float c0 = Cb[n0*128 + m], c1 = Cb[n1*128 + m];
            float c2 = Cb[n2*128 + m], c3 = Cb[n3*128 + m];
            acc = fmaf(xs[n0], c0, acc);
            acc = fmaf(xs[n1], c1, acc);
            acc = fmaf(xs[n2], c2, acc);
            acc = fmaf(xs[n3], c3, acc);
        }
        for (; i < cnt; i++) {
            int n = idxs[i];
            acc = fmaf(xs[n], Cb[n*128 + m], acc);
        }
        g_pre[b*128 + m] = acc;
        gridbar(128);
    }
}

// ---------------- K6: ALL-layer loss partials in ONE pass over B --------
__global__ void k_loss_all(const float* __restrict__ B, const float* __restrict__ z)
{
    const int b   = blockIdx.y;
    const int ch  = blockIdx.x;
    const int tid = threadIdx.x;
    __shared__ float xs[5*128];
    __shared__ float wsum[5][8];

    if (tid < 128) {
#pragma unroll
        for (int l = 0; l < 5; l++)
            xs[l*128 + tid] = g_xeL[(l+1)*16384 + b*128 + tid];
    }
    __syncthreads();

    float acc[5][8];
#pragma unroll
    for (int l = 0; l < 5; l++)
#pragma unroll
        for (int j = 0; j < 8; j++) acc[l][j] = 0.f;

    const float4* Bb = reinterpret_cast<const float4*>(B) + (size_t)b*262144 + ch*512 + tid;

    for (int n = 0; n < 128; n += 2) {
        const float4* p0 = Bb + (size_t)n*2048;
        const float4* p1 = p0 + 2048;
        float4 u0 = p0[0], u1 = p0[256];
        float4 v0 = p1[0], v1 = p1[256];
        float uu[8] = {u0.x,u0.y,u0.z,u0.w,u1.x,u1.y,u1.z,u1.w};
        float vv[8] = {v0.x,v0.y,v0.z,v0.w,v1.x,v1.y,v1.z,v1.w};
#pragma unroll
        for (int l = 0; l < 5; l++) {
            float x0 = xs[l*128 + n];
            float x1 = xs[l*128 + n + 1];
#pragma unroll
            for (int j = 0; j < 8; j++) {
                acc[l][j] = fmaf(x0, uu[j], acc[l][j]);
                acc[l][j] = fmaf(x1, vv[j], acc[l][j]);
            }
        }
    }

    const float4* zp = reinterpret_cast<const float4*>(z) + (size_t)b*2048 + ch*512 + tid;
    float4 z0 = zp[0], z1 = zp[256];
    float zz[8] = {z0.x,z0.y,z0.z,z0.w,z1.x,z1.y,z1.z,z1.w};

#pragma unroll
    for (int l = 0; l < 5; l++) {
        float part = 0.f;
#pragma unroll
        for (int j = 0; j < 8; j++) {
            float e = zz[j] - acc[l][j];
            part = fmaf(e, e, part);
        }
#pragma unroll
        for (int o = 16; o > 0; o >>= 1)
            part += __shfl_down_sync(0xffffffffu, part, o);
        if ((tid & 31) == 0) wsum[l][tid >> 5] = part;
    }
    __syncthreads();
    if (tid == 0) {
#pragma unroll
        for (int l = 0; l < 5; l++) {
            float t = 0.f;
#pragma unroll
            for (int w = 0; w < 8; w++) t += wsum[l][w];
            g_part[(l+1)*512 + b*4 + ch] = t;
        }
    }
}

// ---------------- K7: losses reduction ----------------------------------
__global__ void k_losses(float* __restrict__ out,
                         float s1, float s2, float s3, float s4, float s5)
{
    __shared__ float sm[256];
    const int t = threadIdx.x;  // 1 block, 256 threads
    const float scales[6] = {0.f, s1, s2, s3, s4, s5};
    if (t == 0) out[16384] = 0.f;
    for (int l = 1; l < 6; l++) {
        sm[t] = g_part[l*512 + t] + g_part[l*512 + 256 + t];
        __syncthreads();
        for (int s = 128; s > 0; s >>= 1) {
            if (t < s) sm[t] += sm[t + s];
            __syncthreads();
        }
        if (t == 0) out[16384 + l] = scales[l] * sm[0];
        __syncthreads();
    }
}

// ---------------- launch ------------------------------------------------
extern "C" void kernel_launch(void* const* d_in, const int* in_sizes, int n_in,
                              void* d_out, int out_size)
{
    (void)in_sizes; (void)n_in; (void)out_size;
    const float* BB    = (const float*)d_in[0];
    const float* zB    = (const float*)d_in[1];
    const float* z     = (const float*)d_in[3];
    const float* B     = (const float*)d_in[4];
    const float* x0    = (const float*)d_in[5];
    const float* w_x   = (const float*)d_in[6];
    const float* wKL   = (const float*)d_in[7];
    const float* gamma = (const float*)d_in[8];
    const float* beta  = (const float*)d_in[9];
    float* out = (float*)d_out;

    k_buildC<<<dim3(4,128), 256>>>(BB, wKL);
    k_buildD<<<128, 128>>>(zB, wKL);

    // whole 6-layer recursion in one persistent kernel
    k_chain<<<128, 128>>>(x0, w_x, gamma, beta, out);

    // one dense pass over B computes all 5 nonzero losses
    k_loss_all<<<dim3(4,128), 256>>>(B, z);

    const float inv = 1.0f / 16384.0f;
    k_losses<<<1, 256>>>(out,
        10.0f * logf(2.0f) * inv,
        10.0f * logf(3.0f) * inv,
        10.0f * logf(4.0f) * inv,
        10.0f * logf(5.0f) * inv,
        10.0f * logf(6.0f) * inv);
}